// round 7
// baseline (speedup 1.0000x reference)
#include <cuda_runtime.h>
#include <cuda_bf16.h>
#include <math.h>
#include <float.h>
#include <stdint.h>

// ---------------------------------------------------------------------------
// MultiLabelGCN on GB300 — fused layer, ONE barrier per K-chunk.
// Pipeline per chunk c:  agg[c] -> cp.wait -> bar -> issue W[c+1] -> MMA[c]
//   input chunk c+2 issued via cp.async BEFORE the barrier (triple buffer),
//   W double-buffered, sA2 (A fragments) double-buffered.
// After the barrier warps drift: leaders run agg[c+1] (ALU/FMA/LDS) while
// laggards finish MMA[c] (tensor) — phases overlap across warps.
// ---------------------------------------------------------------------------

#define NUM_JOINTS 33
#define BATCH      4096
#define NN_ROWS    (BATCH * NUM_JOINTS)   // 135168
#define HDIM       256
#define NN_INV     (1.0f / 135168.0f)

#define PANELS 1024
#define PROWS  132
#define MPAD   160

// smem layout (bytes)
#define OFF_IN     0                        // float [3][132][36]   57024
#define OFF_A2     57024                    // u32 [2][160*40]      51200
#define OFF_B      108224                   // u32 [2][256*40]      81920
#define OFF_SCALE  190144                   // float [256]           1024
#define OFF_SHIFT  191168                   // float [256]           1024
#define OFF_STAT   192192                   // float [512]           2048
#define OFF_NW     194240                   // float [103]            512
#define SMEM_BYTES 194816

__constant__ int ADJ_OFF[34] = {
    0,3,6,9,12,15,18,21,23,25,27,29,33,37,40,43,48,53,56,59,62,65,
    67,69,73,77,80,83,87,91,94,97,100,103};
__constant__ int ADJ_NB[103] = {
    1,4,0,  0,2,1,  1,3,2,  2,7,3,  0,5,4,  4,6,5,  5,8,6,  3,7,  6,8,
    10,9,  9,10,  12,13,23,11,  11,14,24,12,  11,15,13,  12,16,14,
    13,17,19,21,15,  14,18,20,22,16,  15,19,17,  16,20,18,  15,17,19,
    16,18,20,  15,21,  16,22,  11,24,25,23,  12,23,26,24,  23,27,25,
    24,28,26,  25,29,31,27,  26,30,32,28,  27,31,29,  28,32,30,
    29,27,31,  30,28,32};
__constant__ float DEGF[33] = {
    3,3,3,3,3,3,3,2,2,2,2,4,4,3,3,5,5,3,3,3,3,2,2,4,4,3,3,4,4,3,3,3,3};
// row -> node id / graph base row (4 graphs per panel)
__constant__ unsigned char ROW_N[132] = {
    0,1,2,3,4,5,6,7,8,9,10,11,12,13,14,15,16,17,18,19,20,21,22,23,24,25,26,27,28,29,30,31,32,
    0,1,2,3,4,5,6,7,8,9,10,11,12,13,14,15,16,17,18,19,20,21,22,23,24,25,26,27,28,29,30,31,32,
    0,1,2,3,4,5,6,7,8,9,10,11,12,13,14,15,16,17,18,19,20,21,22,23,24,25,26,27,28,29,30,31,32,
    0,1,2,3,4,5,6,7,8,9,10,11,12,13,14,15,16,17,18,19,20,21,22,23,24,25,26,27,28,29,30,31,32};
__constant__ unsigned char ROW_GB[132] = {
    0,0,0,0,0,0,0,0,0,0,0,0,0,0,0,0,0,0,0,0,0,0,0,0,0,0,0,0,0,0,0,0,0,
    33,33,33,33,33,33,33,33,33,33,33,33,33,33,33,33,33,33,33,33,33,33,33,33,33,33,33,33,33,33,33,33,33,
    66,66,66,66,66,66,66,66,66,66,66,66,66,66,66,66,66,66,66,66,66,66,66,66,66,66,66,66,66,66,66,66,66,
    99,99,99,99,99,99,99,99,99,99,99,99,99,99,99,99,99,99,99,99,99,99,99,99,99,99,99,99,99,99,99,99,99};

// scratch
__device__ float g_bufA[(size_t)NN_ROWS * HDIM];
__device__ float g_bufB[(size_t)NN_ROWS * HDIM];
__device__ float g_stats[3 * 512];
__device__ uint2 g_wpack[4 * 8 * 256 * 16];   // [mat][chunk][col][kp]

// ---------------------------------------------------------------------------
__device__ __forceinline__ uint32_t f2tf32(float f) {
    uint32_t u;
    asm("cvt.rna.tf32.f32 %0, %1;" : "=r"(u) : "f"(f));
    return u;
}
__device__ __forceinline__ void mma_tf32(float* d, const uint32_t* a, const uint32_t* b) {
    asm volatile(
        "mma.sync.aligned.m16n8k8.row.col.f32.tf32.tf32.f32 "
        "{%0,%1,%2,%3}, {%4,%5,%6,%7}, {%8,%9}, {%0,%1,%2,%3};\n"
        : "+f"(d[0]), "+f"(d[1]), "+f"(d[2]), "+f"(d[3])
        : "r"(a[0]), "r"(a[1]), "r"(a[2]), "r"(a[3]), "r"(b[0]), "r"(b[1]));
}
__device__ __forceinline__ void cp16(void* dst, const void* src) {
    uint32_t d = (uint32_t)__cvta_generic_to_shared(dst);
    asm volatile("cp.async.cg.shared.global [%0], [%1], 16;\n" :: "r"(d), "l"(src));
}
#define CP_COMMIT() asm volatile("cp.async.commit_group;\n")
#define CP_WAIT1()  asm volatile("cp.async.wait_group 1;\n")
#define CP_WAIT2()  asm volatile("cp.async.wait_group 2;\n")

// ---------------------------------------------------------------------------
__global__ void pack_w(const float* __restrict__ w0, const float* __restrict__ w1,
                       const float* __restrict__ w2, const float* __restrict__ wh)
{
    int idx = blockIdx.x * blockDim.x + threadIdx.x;   // 0..131071
    int kp  = idx & 15;
    int col = (idx >> 4) & 255;
    int c0  = (idx >> 12) & 7;
    int m   = idx >> 15;
    const float* W = (m == 0) ? w0 : (m == 1) ? w1 : (m == 2) ? w2 : wh;
    int k = c0 * 32 + ((kp >> 2) * 8) + (kp & 3);
    uint2 v;
    v.x = f2tf32(W[(size_t)k * HDIM + col]);
    v.y = f2tf32(W[(size_t)(k + 4) * HDIM + col]);
    g_wpack[idx] = v;
}

__global__ void zero_stats_kernel(float* stats) {
    int i = blockIdx.x * blockDim.x + threadIdx.x;
    if (i < 3 * 512) stats[i] = 0.0f;
}

// ---------------------------------------------------------------------------
// fused layer. grid = PANELS, block = 512, dyn smem SMEM_BYTES.
// ---------------------------------------------------------------------------
__global__ void __launch_bounds__(512, 1)
fused_layer(const float* __restrict__ in, int wsel, const float* __restrict__ bias,
            float* __restrict__ out, const float* __restrict__ stats_in,
            const float* __restrict__ gam, const float* __restrict__ bet,
            float* __restrict__ stats_out, int mode)
{
    extern __shared__ char smem[];
    float*    sIn   = (float*)(smem + OFF_IN);     // [3][132][36]
    uint32_t* sA2   = (uint32_t*)(smem + OFF_A2);  // [2][160*40]
    uint32_t* sB2   = (uint32_t*)(smem + OFF_B);   // [2][256*40]
    float*    sScale= (float*)(smem + OFF_SCALE);
    float*    sShift= (float*)(smem + OFF_SHIFT);
    float*    sStat = (float*)(smem + OFF_STAT);
    float*    sNW   = (float*)(smem + OFF_NW);

    const int tid = threadIdx.x, lane = tid & 31, warp = tid >> 5;
    const int wm = warp >> 3, wn = warp & 7;
    const int p = blockIdx.x;
    const float* src = in + (size_t)p * PROWS * HDIM;
    const uint2* wbase = g_wpack + (size_t)wsel * (8 * 256 * 16);

    // ---- init ----
    if (tid < NUM_JOINTS) {
        float dn = rsqrtf(DEGF[tid]);
        for (int e = ADJ_OFF[tid]; e < ADJ_OFF[tid + 1]; e++)
            sNW[e] = dn * rsqrtf(DEGF[ADJ_NB[e]]);
    }
    if (tid < 256) {
        if (mode == 1) {
            float mu  = stats_in[tid] * NN_INV;
            float ex2 = stats_in[256 + tid] * NN_INV;
            float inv = rsqrtf(ex2 - mu * mu + 1e-5f);
            float sc  = inv * gam[tid];
            sScale[tid] = sc;
            sShift[tid] = bet[tid] - mu * sc;
        } else {
            sScale[tid] = 1.0f;
            sShift[tid] = 0.0f;
        }
    }
    sStat[tid] = 0.0f;
    // zero pad rows of BOTH sA2 buffers (rows 132..159, never rewritten)
    for (int i = tid; i < (MPAD - PROWS) * 40; i += 512) {
        sA2[PROWS * 40 + i] = 0;
        sA2[6400 + PROWS * 40 + i] = 0;
    }

    // ---- prologue: stage in[0], in[1], W[0] as three groups ----
    for (int j = tid; j < 1056; j += 512) {           // in[0] -> buf 0
        int r = j >> 3, seg = j & 7;
        cp16((char*)sIn + r * 144 + seg * 16,
             (const char*)(src + (size_t)r * HDIM + seg * 4));
    }
    CP_COMMIT();
    for (int j = tid; j < 1056; j += 512) {           // in[1] -> buf 1
        int r = j >> 3, seg = j & 7;
        cp16((char*)sIn + 19008 + r * 144 + seg * 16,
             (const char*)(src + (size_t)r * HDIM + 32 + seg * 4));
    }
    CP_COMMIT();
    for (int j = tid; j < 2048; j += 512) {           // W[0] -> buf 0
        int col = j >> 3, seg = j & 7;
        cp16((char*)sB2 + col * 160 + seg * 16,
             (const char*)(wbase + (size_t)col * 16 + seg * 2));
    }
    CP_COMMIT();
    CP_WAIT2();                // in[0] complete
    __syncthreads();           // visible to all; init done

    float acc[5][4][4];
    #pragma unroll
    for (int i = 0; i < 5; i++)
        #pragma unroll
        for (int nt = 0; nt < 4; nt++)
            #pragma unroll
            for (int j = 0; j < 4; j++) acc[i][nt][j] = 0.0f;

    const int widx = ((lane >> 3) * 4 + (lane & 3)) * 2 + ((lane >> 2) & 1);
    int bin = 0;               // c % 3

    for (int c = 0; c < 8; c++) {
        const int k0 = c * 32;

        // ---- step 1: agg[c] : sIn[bin] -> sA2[c&1] (tf32 fragments) ----
        {
            const float* sInc = sIn + bin * (132 * 36);
            uint32_t* sAc = sA2 + (c & 1) * 6400;
            const float scl = sScale[k0 + lane];
            const float shf = sShift[k0 + lane];
            for (int r = warp; r < PROWS; r += 16) {
                int n  = ROW_N[r];
                int gb = ROW_GB[r];
                float a = 0.0f;
                int e1 = ADJ_OFF[n + 1];
                for (int e = ADJ_OFF[n]; e < e1; e++) {
                    float f = sInc[(gb + ADJ_NB[e]) * 36 + lane];
                    if (mode == 0) {
                        if (isnan(f)) f = 0.0f;
                        else if (isinf(f)) f = (f > 0.0f) ? FLT_MAX : -FLT_MAX;
                    } else {
                        f = fmaxf(fmaf(f, scl, shf), 0.0f);
                    }
                    a = fmaf(sNW[e], f, a);
                }
                sAc[r * 40 + widx] = f2tf32(a);
            }
        }

        // ---- step 2: issue in[c+2] (victim buffer last read 2 bars ago) ----
        if (c + 2 < 8) {
            int b2 = (c + 2) % 3;
            const float* srcN = src + (c + 2) * 32;
            float* dstN = sIn + b2 * (132 * 36);
            for (int j = tid; j < 1056; j += 512) {
                int r = j >> 3, seg = j & 7;
                cp16((char*)dstN + r * 144 + seg * 16,
                     (const char*)(srcN + (size_t)r * HDIM + seg * 4));
            }
        }
        CP_COMMIT();   // unconditional: uniform group accounting

        // ---- step 3+4: retire in[c+1] & W[c] (leave newest group), sync ----
        CP_WAIT1();
        __syncthreads();   // THE barrier: sA2[c&1] visible, staged data visible

        // ---- step 5: issue W[c+1] (victim read by MMA[c-1], pre-barrier) ----
        if (c + 1 < 8) {
            uint32_t* sBn = sB2 + ((c + 1) & 1) * 10240;
            const uint2* wbN = wbase + (size_t)(c + 1) * 256 * 16;
            for (int j = tid; j < 2048; j += 512) {
                int col = j >> 3, seg = j & 7;
                cp16((char*)sBn + col * 160 + seg * 16,
                     (const char*)(wbN + (size_t)col * 16 + seg * 2));
            }
        }
        CP_COMMIT();

        // ---- step 6: MMA[c] from sA2[c&1] + sB2[c&1] ----
        {
            uint32_t* sAc = sA2 + (c & 1) * 6400;
            uint32_t* sBcur = sB2 + (c & 1) * 10240;
            #pragma unroll
            for (int ks = 0; ks < 4; ks++) {
                uint2 bfr[4];
                #pragma unroll
                for (int nt = 0; nt < 4; nt++) {
                    int col_l = wn * 32 + nt * 8 + (lane >> 2);
                    bfr[nt] = *(const uint2*)&sBcur[col_l * 40 + (ks * 4 + (lane & 3)) * 2];
                }
                #pragma unroll
                for (int i = 0; i < 5; i++) {
                    int r = wm * 80 + i * 16 + (lane >> 2);
                    uint2 p0 = *(const uint2*)&sAc[r * 40 + (ks * 4 + (lane & 3)) * 2];
                    uint2 p1 = *(const uint2*)&sAc[(r + 8) * 40 + (ks * 4 + (lane & 3)) * 2];
                    uint32_t af[4] = {p0.x, p1.x, p0.y, p1.y};
                    #pragma unroll
                    for (int nt = 0; nt < 4; nt++)
                        mma_tf32(acc[i][nt], af, (const uint32_t*)&bfr[nt]);
                }
            }
        }

        bin = (bin == 2) ? 0 : bin + 1;
    }

    // ---- epilogue: bias, store, stats ----
    float bval[8];
    #pragma unroll
    for (int nt = 0; nt < 4; nt++) {
        int col = wn * 32 + nt * 8 + 2 * (lane & 3);
        bval[nt * 2 + 0] = bias[col];
        bval[nt * 2 + 1] = bias[col + 1];
    }
    float cs1[8], cs2[8];
    #pragma unroll
    for (int j = 0; j < 8; j++) { cs1[j] = 0.0f; cs2[j] = 0.0f; }

    #pragma unroll
    for (int i = 0; i < 5; i++) {
        int rb = wm * 80 + i * 16 + (lane >> 2);
        #pragma unroll
        for (int nt = 0; nt < 4; nt++) {
            int col = wn * 32 + nt * 8 + 2 * (lane & 3);
            if (rb < PROWS) {
                float z0 = acc[i][nt][0] + bval[nt * 2 + 0];
                float z1 = acc[i][nt][1] + bval[nt * 2 + 1];
                *(float2*)(out + (size_t)(p * PROWS + rb) * HDIM + col) = make_float2(z0, z1);
                cs1[nt * 2 + 0] += z0; cs2[nt * 2 + 0] = fmaf(z0, z0, cs2[nt * 2 + 0]);
                cs1[nt * 2 + 1] += z1; cs2[nt * 2 + 1] = fmaf(z1, z1, cs2[nt * 2 + 1]);
            }
            int r2 = rb + 8;
            if (r2 < PROWS) {
                float z2 = acc[i][nt][2] + bval[nt * 2 + 0];
                float z3 = acc[i][nt][3] + bval[nt * 2 + 1];
                *(float2*)(out + (size_t)(p * PROWS + r2) * HDIM + col) = make_float2(z2, z3);
                cs1[nt * 2 + 0] += z2; cs2[nt * 2 + 0] = fmaf(z2, z2, cs2[nt * 2 + 0]);
                cs1[nt * 2 + 1] += z3; cs2[nt * 2 + 1] = fmaf(z3, z3, cs2[nt * 2 + 1]);
            }
        }
    }

    if (stats_out != nullptr) {
        #pragma unroll
        for (int j = 0; j < 8; j++) {
            int cl = wn * 32 + (j >> 1) * 8 + 2 * (lane & 3) + (j & 1);
            atomicAdd(&sStat[cl], cs1[j]);
            atomicAdd(&sStat[256 + cl], cs2[j]);
        }
        __syncthreads();
        if (tid < 256) {
            atomicAdd(&stats_out[tid], sStat[tid]);
            atomicAdd(&stats_out[256 + tid], sStat[256 + tid]);
        }
    }
}

// ---------------------------------------------------------------------------
__global__ void __launch_bounds__(256)
pool_kernel(const float* __restrict__ h, const float* __restrict__ wc,
            const float* __restrict__ bc, float* __restrict__ out)
{
    const int g = blockIdx.x;
    const int tid = threadIdx.x;
    const int lane = tid & 31, warp = tid >> 5;
    const size_t base = (size_t)g * NUM_JOINTS * HDIM;

    float s = 0.0f;
    #pragma unroll
    for (int n = 0; n < NUM_JOINTS; n++) s += h[base + n * HDIM + tid];
    s *= (1.0f / 33.0f);

    float4 wv = *(const float4*)(wc + tid * 4);
    float p0 = s * wv.x, p1 = s * wv.y, p2 = s * wv.z, p3 = s * wv.w;
    #pragma unroll
    for (int off = 16; off > 0; off >>= 1) {
        p0 += __shfl_down_sync(0xFFFFFFFF, p0, off);
        p1 += __shfl_down_sync(0xFFFFFFFF, p1, off);
        p2 += __shfl_down_sync(0xFFFFFFFF, p2, off);
        p3 += __shfl_down_sync(0xFFFFFFFF, p3, off);
    }
    __shared__ float4 part[8];
    if (lane == 0) part[warp] = make_float4(p0, p1, p2, p3);
    __syncthreads();
    if (tid == 0) {
        float4 t = make_float4(bc[0], bc[1], bc[2], bc[3]);
        #pragma unroll
        for (int w = 0; w < 8; w++) {
            t.x += part[w].x; t.y += part[w].y; t.z += part[w].z; t.w += part[w].w;
        }
        *(float4*)(out + g * 4) = t;
    }
}

// ---------------------------------------------------------------------------
extern "C" void kernel_launch(void* const* d_in, const int* in_sizes, int n_in,
                              void* d_out, int out_size)
{
    const float* x   = (const float*)d_in[0];
    const float* w0  = (const float*)d_in[1];
    const float* b0  = (const float*)d_in[2];
    const float* g0  = (const float*)d_in[3];
    const float* be0 = (const float*)d_in[4];
    const float* w1  = (const float*)d_in[5];
    const float* b1  = (const float*)d_in[6];
    const float* g1  = (const float*)d_in[7];
    const float* be1 = (const float*)d_in[8];
    const float* w2  = (const float*)d_in[9];
    const float* b2  = (const float*)d_in[10];
    const float* g2  = (const float*)d_in[11];
    const float* be2 = (const float*)d_in[12];
    const float* wh  = (const float*)d_in[13];
    const float* bh  = (const float*)d_in[14];
    const float* wc  = (const float*)d_in[15];
    const float* bc  = (const float*)d_in[16];

    float *bufA, *bufB, *stats;
    cudaGetSymbolAddress((void**)&bufA, g_bufA);
    cudaGetSymbolAddress((void**)&bufB, g_bufB);
    cudaGetSymbolAddress((void**)&stats, g_stats);

    cudaFuncSetAttribute(fused_layer, cudaFuncAttributeMaxDynamicSharedMemorySize,
                         SMEM_BYTES);

    pack_w<<<512, 256>>>(w0, w1, w2, wh);
    zero_stats_kernel<<<6, 256>>>(stats);

    fused_layer<<<PANELS, 512, SMEM_BYTES>>>(x,    0, b0, bufB, nullptr, nullptr, nullptr, stats, 0);
    fused_layer<<<PANELS, 512, SMEM_BYTES>>>(bufB, 1, b1, bufA, stats,        g0, be0, stats + 512, 1);
    fused_layer<<<PANELS, 512, SMEM_BYTES>>>(bufA, 2, b2, bufB, stats + 512,  g1, be1, stats + 1024, 1);
    fused_layer<<<PANELS, 512, SMEM_BYTES>>>(bufB, 3, bh, bufA, stats + 1024, g2, be2, nullptr, 1);
    pool_kernel<<<BATCH, 256>>>(bufA, wc, bc, (float*)d_out);
}

// round 9
// speedup vs baseline: 1.1790x; 1.1790x over previous
#include <cuda_runtime.h>
#include <cuda_bf16.h>
#include <math.h>
#include <float.h>
#include <stdint.h>

// ---------------------------------------------------------------------------
// MultiLabelGCN on GB300 — small-CTA fused layers (2 CTAs/SM overlap).
// Per CTA: M = 66 rows (2 whole graphs), N = 256, K in 8 chunks of 32.
//   input triple-buffered via cp.async, agg (BN+ReLU+stencil) -> tf32
//   fragments in smem, B fragments via direct LDG.64 from packed W (L2),
//   m16n8k8 tf32 MMA, stats in epilogue.
// ---------------------------------------------------------------------------

#define NUM_JOINTS 33
#define BATCH      4096
#define NN_ROWS    (BATCH * NUM_JOINTS)   // 135168
#define HDIM       256
#define NN_INV     (1.0f / 135168.0f)

#define NTILES (NN_ROWS / 66)       // 2048 CTAs
#define TROWS  66                   // 2 graphs
#define MPAD   80                   // 5 x m16

// smem layout (bytes)
#define OFF_IN     0                        // float [3][66][36]   28512
#define INBUF      9504
#define OFF_A2     28512                    // u32 [2][80*40]      25600
#define OFF_SCALE  54112                    // float [256]          1024
#define OFF_SHIFT  55136                    // float [256]          1024
#define OFF_STAT   56160                    // float [512]          2048
#define OFF_NW     58208                    // float [103] + pad     512
#define SMEM_BYTES 58720

__constant__ int ADJ_OFF[34] = {
    0,3,6,9,12,15,18,21,23,25,27,29,33,37,40,43,48,53,56,59,62,65,
    67,69,73,77,80,83,87,91,94,97,100,103};
__constant__ int ADJ_NB[103] = {
    1,4,0,  0,2,1,  1,3,2,  2,7,3,  0,5,4,  4,6,5,  5,8,6,  3,7,  6,8,
    10,9,  9,10,  12,13,23,11,  11,14,24,12,  11,15,13,  12,16,14,
    13,17,19,21,15,  14,18,20,22,16,  15,19,17,  16,20,18,  15,17,19,
    16,18,20,  15,21,  16,22,  11,24,25,23,  12,23,26,24,  23,27,25,
    24,28,26,  25,29,31,27,  26,30,32,28,  27,31,29,  28,32,30,
    29,27,31,  30,28,32};
__constant__ float DEGF[33] = {
    3,3,3,3,3,3,3,2,2,2,2,4,4,3,3,5,5,3,3,3,3,2,2,4,4,3,3,4,4,3,3,3,3};

// scratch
__device__ float g_bufA[(size_t)NN_ROWS * HDIM];
__device__ float g_bufB[(size_t)NN_ROWS * HDIM];
__device__ float g_stats[3 * 512];
__device__ uint2 g_wpack[4 * 8 * 256 * 16];   // [mat][chunk][col][kp]

// ---------------------------------------------------------------------------
__device__ __forceinline__ uint32_t f2tf32(float f) {
    uint32_t u;
    asm("cvt.rna.tf32.f32 %0, %1;" : "=r"(u) : "f"(f));
    return u;
}
__device__ __forceinline__ void mma_tf32(float* d, const uint32_t* a, const uint32_t* b) {
    asm volatile(
        "mma.sync.aligned.m16n8k8.row.col.f32.tf32.tf32.f32 "
        "{%0,%1,%2,%3}, {%4,%5,%6,%7}, {%8,%9}, {%0,%1,%2,%3};\n"
        : "+f"(d[0]), "+f"(d[1]), "+f"(d[2]), "+f"(d[3])
        : "r"(a[0]), "r"(a[1]), "r"(a[2]), "r"(a[3]), "r"(b[0]), "r"(b[1]));
}
__device__ __forceinline__ void cp16(void* dst, const void* src) {
    uint32_t d = (uint32_t)__cvta_generic_to_shared(dst);
    asm volatile("cp.async.cg.shared.global [%0], [%1], 16;\n" :: "r"(d), "l"(src));
}
#define CP_COMMIT() asm volatile("cp.async.commit_group;\n")
#define CP_WAIT1()  asm volatile("cp.async.wait_group 1;\n")

// ---------------------------------------------------------------------------
// pack weights -> tf32 pairs: [mat][chunk c0][col][kp], k = c0*32+(kp>>2)*8+(kp&3)
// ---------------------------------------------------------------------------
__global__ void pack_w(const float* __restrict__ w0, const float* __restrict__ w1,
                       const float* __restrict__ w2, const float* __restrict__ wh)
{
    int idx = blockIdx.x * blockDim.x + threadIdx.x;   // 0..131071
    int kp  = idx & 15;
    int col = (idx >> 4) & 255;
    int c0  = (idx >> 12) & 7;
    int m   = idx >> 15;
    const float* W = (m == 0) ? w0 : (m == 1) ? w1 : (m == 2) ? w2 : wh;
    int k = c0 * 32 + ((kp >> 2) * 8) + (kp & 3);
    uint2 v;
    v.x = f2tf32(W[(size_t)k * HDIM + col]);
    v.y = f2tf32(W[(size_t)(k + 4) * HDIM + col]);
    g_wpack[idx] = v;
}

__global__ void zero_stats_kernel(float* stats) {
    int i = blockIdx.x * blockDim.x + threadIdx.x;
    if (i < 3 * 512) stats[i] = 0.0f;
}

// ---------------------------------------------------------------------------
// fused layer. grid = NTILES (2048), block = 256, 2 CTAs/SM.
// ---------------------------------------------------------------------------
__global__ void __launch_bounds__(256, 2)
fused_layer(const float* __restrict__ in, int wsel, const float* __restrict__ bias,
            float* __restrict__ out, const float* __restrict__ stats_in,
            const float* __restrict__ gam, const float* __restrict__ bet,
            float* __restrict__ stats_out, int mode)
{
    extern __shared__ char smem[];
    float*    sIn   = (float*)(smem + OFF_IN);     // [3][66][36]
    uint32_t* sA2   = (uint32_t*)(smem + OFF_A2);  // [2][80*40]
    float*    sScale= (float*)(smem + OFF_SCALE);
    float*    sShift= (float*)(smem + OFF_SHIFT);
    float*    sStat = (float*)(smem + OFF_STAT);
    float*    sNW   = (float*)(smem + OFF_NW);

    const int tid = threadIdx.x, lane = tid & 31, warp = tid >> 5;   // 8 warps
    const int p = blockIdx.x;
    const int rowBase = p * TROWS;
    const float* src = in + (size_t)rowBase * HDIM;
    const uint2* wbase = g_wpack + (size_t)wsel * (8 * 256 * 16);

    // ---- init ----
    if (tid < NUM_JOINTS) {
        float dn = rsqrtf(DEGF[tid]);
        for (int e = ADJ_OFF[tid]; e < ADJ_OFF[tid + 1]; e++)
            sNW[e] = dn * rsqrtf(DEGF[ADJ_NB[e]]);
    }
    if (mode == 1) {
        float mu  = stats_in[tid] * NN_INV;
        float ex2 = stats_in[256 + tid] * NN_INV;
        float inv = rsqrtf(ex2 - mu * mu + 1e-5f);
        float sc  = inv * gam[tid];
        sScale[tid] = sc;
        sShift[tid] = bet[tid] - mu * sc;
    } else {
        sScale[tid] = 1.0f;
        sShift[tid] = 0.0f;
    }
    sStat[tid] = 0.0f;
    sStat[256 + tid] = 0.0f;
    // zero pad rows (66..79) of both sA2 buffers; never rewritten
    for (int i = tid; i < (MPAD - TROWS) * 40; i += 256) {
        sA2[TROWS * 40 + i] = 0;
        sA2[3200 + TROWS * 40 + i] = 0;
    }

    // ---- prologue: stage in[0], in[1] ----
    for (int j = tid; j < TROWS * 8; j += 256) {
        int r = j >> 3, seg = j & 7;
        cp16((char*)sIn + r * 144 + seg * 16, src + (size_t)r * HDIM + seg * 4);
    }
    CP_COMMIT();
    for (int j = tid; j < TROWS * 8; j += 256) {
        int r = j >> 3, seg = j & 7;
        cp16((char*)sIn + INBUF + r * 144 + seg * 16,
             src + (size_t)r * HDIM + 32 + seg * 4);
    }
    CP_COMMIT();

    float acc[5][4][4];
    #pragma unroll
    for (int i = 0; i < 5; i++)
        #pragma unroll
        for (int nt = 0; nt < 4; nt++)
            #pragma unroll
            for (int j = 0; j < 4; j++) acc[i][nt][j] = 0.0f;

    const int widx = ((lane >> 3) * 4 + (lane & 3)) * 2 + ((lane >> 2) & 1);

    for (int c = 0; c < 8; c++) {
        CP_WAIT1();
        __syncthreads();   // in[c] staged + visible; sA[c&1] free (MMA[c-2] done)

        // issue in[c+2]
        if (c + 2 < 8) {
            char* dI = (char*)sIn + ((c + 2) % 3) * INBUF;
            const float* sN = src + (c + 2) * 32;
            for (int j = tid; j < TROWS * 8; j += 256) {
                int r = j >> 3, seg = j & 7;
                cp16(dI + r * 144 + seg * 16, sN + (size_t)r * HDIM + seg * 4);
            }
        }
        CP_COMMIT();       // unconditional: uniform group accounting

        // ---- agg[c]: sIn[c%3] -> sA2[c&1] (tf32 fragments) ----
        {
            const float* sInc = sIn + (c % 3) * (66 * 36) ;
            uint32_t* sAc = sA2 + (c & 1) * 3200;
            const float scl = sScale[c * 32 + lane];
            const float shf = sShift[c * 32 + lane];
            for (int r = warp; r < TROWS; r += 8) {
                int n  = (r >= NUM_JOINTS) ? r - NUM_JOINTS : r;
                int lb = (r >= NUM_JOINTS) ? NUM_JOINTS : 0;
                float a = 0.0f;
                int e1 = ADJ_OFF[n + 1];
                for (int e = ADJ_OFF[n]; e < e1; e++) {
                    float f = sInc[(lb + ADJ_NB[e]) * 36 + lane];
                    if (mode == 0) {
                        if (isnan(f)) f = 0.0f;
                        else if (isinf(f)) f = (f > 0.0f) ? FLT_MAX : -FLT_MAX;
                    } else {
                        f = fmaxf(fmaf(f, scl, shf), 0.0f);
                    }
                    a = fmaf(sNW[e], f, a);
                }
                sAc[r * 40 + widx] = f2tf32(a);
            }
        }
        __syncthreads();   // sA2[c&1] ready

        // ---- MMA[c]: A from smem (LDS.64), B from gmem/L2 (LDG.64) ----
        {
            const uint32_t* sAc = sA2 + (c & 1) * 3200;
            const uint2* wc_ = wbase + (size_t)c * 256 * 16;
            #pragma unroll
            for (int ks = 0; ks < 4; ks++) {
                uint2 bfr[4];
                #pragma unroll
                for (int nt = 0; nt < 4; nt++) {
                    int col = warp * 32 + nt * 8 + (lane >> 2);
                    bfr[nt] = __ldg(&wc_[col * 16 + ks * 4 + (lane & 3)]);
                }
                #pragma unroll
                for (int i = 0; i < 5; i++) {
                    int r = i * 16 + (lane >> 2);
                    uint2 p0 = *(const uint2*)&sAc[r * 40 + (ks * 4 + (lane & 3)) * 2];
                    uint2 p1 = *(const uint2*)&sAc[(r + 8) * 40 + (ks * 4 + (lane & 3)) * 2];
                    uint32_t af[4] = {p0.x, p1.x, p0.y, p1.y};
                    #pragma unroll
                    for (int nt = 0; nt < 4; nt++)
                        mma_tf32(acc[i][nt], af, (const uint32_t*)&bfr[nt]);
                }
            }
        }
    }

    // ---- epilogue: bias, store, stats (warp covers cols warp*32..+31) ----
    float bval[8];
    #pragma unroll
    for (int nt = 0; nt < 4; nt++) {
        int col = warp * 32 + nt * 8 + 2 * (lane & 3);
        bval[nt * 2 + 0] = bias[col];
        bval[nt * 2 + 1] = bias[col + 1];
    }
    float cs1[8], cs2[8];
    #pragma unroll
    for (int j = 0; j < 8; j++) { cs1[j] = 0.0f; cs2[j] = 0.0f; }

    #pragma unroll
    for (int i = 0; i < 5; i++) {
        int rb = i * 16 + (lane >> 2);
        #pragma unroll
        for (int nt = 0; nt < 4; nt++) {
            int col = warp * 32 + nt * 8 + 2 * (lane & 3);
            if (rb < TROWS) {
                float z0 = acc[i][nt][0] + bval[nt * 2 + 0];
                float z1 = acc[i][nt][1] + bval[nt * 2 + 1];
                *(float2*)(out + (size_t)(rowBase + rb) * HDIM + col) = make_float2(z0, z1);
                cs1[nt * 2 + 0] += z0; cs2[nt * 2 + 0] = fmaf(z0, z0, cs2[nt * 2 + 0]);
                cs1[nt * 2 + 1] += z1; cs2[nt * 2 + 1] = fmaf(z1, z1, cs2[nt * 2 + 1]);
            }
            int r2 = rb + 8;
            if (r2 < TROWS) {
                float z2 = acc[i][nt][2] + bval[nt * 2 + 0];
                float z3 = acc[i][nt][3] + bval[nt * 2 + 1];
                *(float2*)(out + (size_t)(rowBase + r2) * HDIM + col) = make_float2(z2, z3);
                cs1[nt * 2 + 0] += z2; cs2[nt * 2 + 0] = fmaf(z2, z2, cs2[nt * 2 + 0]);
                cs1[nt * 2 + 1] += z3; cs2[nt * 2 + 1] = fmaf(z3, z3, cs2[nt * 2 + 1]);
            }
        }
    }

    if (stats_out != nullptr) {
        #pragma unroll
        for (int j = 0; j < 8; j++) {
            int cl = warp * 32 + (j >> 1) * 8 + 2 * (lane & 3) + (j & 1);
            atomicAdd(&sStat[cl], cs1[j]);
            atomicAdd(&sStat[256 + cl], cs2[j]);
        }
        __syncthreads();
        atomicAdd(&stats_out[tid], sStat[tid]);
        atomicAdd(&stats_out[256 + tid], sStat[256 + tid]);
    }
}

// ---------------------------------------------------------------------------
__global__ void __launch_bounds__(256)
pool_kernel(const float* __restrict__ h, const float* __restrict__ wc,
            const float* __restrict__ bc, float* __restrict__ out)
{
    const int g = blockIdx.x;
    const int tid = threadIdx.x;
    const int lane = tid & 31, warp = tid >> 5;
    const size_t base = (size_t)g * NUM_JOINTS * HDIM;

    float s = 0.0f;
    #pragma unroll
    for (int n = 0; n < NUM_JOINTS; n++) s += h[base + n * HDIM + tid];
    s *= (1.0f / 33.0f);

    float4 wv = *(const float4*)(wc + tid * 4);
    float p0 = s * wv.x, p1 = s * wv.y, p2 = s * wv.z, p3 = s * wv.w;
    #pragma unroll
    for (int off = 16; off > 0; off >>= 1) {
        p0 += __shfl_down_sync(0xFFFFFFFF, p0, off);
        p1 += __shfl_down_sync(0xFFFFFFFF, p1, off);
        p2 += __shfl_down_sync(0xFFFFFFFF, p2, off);
        p3 += __shfl_down_sync(0xFFFFFFFF, p3, off);
    }
    __shared__ float4 part[8];
    if (lane == 0) part[warp] = make_float4(p0, p1, p2, p3);
    __syncthreads();
    if (tid == 0) {
        float4 o = make_float4(bc[0], bc[1], bc[2], bc[3]);
        #pragma unroll
        for (int w = 0; w < 8; w++) {
            o.x += part[w].x; o.y += part[w].y; o.z += part[w].z; o.w += part[w].w;
        }
        *(float4*)(out + g * 4) = o;
    }
}

// ---------------------------------------------------------------------------
extern "C" void kernel_launch(void* const* d_in, const int* in_sizes, int n_in,
                              void* d_out, int out_size)
{
    const float* x   = (const float*)d_in[0];
    const float* w0  = (const float*)d_in[1];
    const float* b0  = (const float*)d_in[2];
    const float* g0  = (const float*)d_in[3];
    const float* be0 = (const float*)d_in[4];
    const float* w1  = (const float*)d_in[5];
    const float* b1  = (const float*)d_in[6];
    const float* g1  = (const float*)d_in[7];
    const float* be1 = (const float*)d_in[8];
    const float* w2  = (const float*)d_in[9];
    const float* b2  = (const float*)d_in[10];
    const float* g2  = (const float*)d_in[11];
    const float* be2 = (const float*)d_in[12];
    const float* wh  = (const float*)d_in[13];
    const float* bh  = (const float*)d_in[14];
    const float* wc  = (const float*)d_in[15];
    const float* bc  = (const float*)d_in[16];

    float *bufA, *bufB, *stats;
    cudaGetSymbolAddress((void**)&bufA, g_bufA);
    cudaGetSymbolAddress((void**)&bufB, g_bufB);
    cudaGetSymbolAddress((void**)&stats, g_stats);

    cudaFuncSetAttribute(fused_layer, cudaFuncAttributeMaxDynamicSharedMemorySize,
                         SMEM_BYTES);

    pack_w<<<512, 256>>>(w0, w1, w2, wh);
    zero_stats_kernel<<<6, 256>>>(stats);

    fused_layer<<<NTILES, 256, SMEM_BYTES>>>(x,    0, b0, bufB, nullptr, nullptr, nullptr, stats, 0);
    fused_layer<<<NTILES, 256, SMEM_BYTES>>>(bufB, 1, b1, bufA, stats,        g0, be0, stats + 512, 1);
    fused_layer<<<NTILES, 256, SMEM_BYTES>>>(bufA, 2, b2, bufB, stats + 512,  g1, be1, stats + 1024, 1);
    fused_layer<<<NTILES, 256, SMEM_BYTES>>>(bufB, 3, bh, bufA, stats + 1024, g2, be2, nullptr, 1);
    pool_kernel<<<BATCH, 256>>>(bufA, wc, bc, (float*)d_out);
}

// round 10
// speedup vs baseline: 1.5838x; 1.3434x over previous
#include <cuda_runtime.h>
#include <cuda_bf16.h>
#include <cuda_fp16.h>
#include <math.h>
#include <float.h>
#include <stdint.h>

// ---------------------------------------------------------------------------
// MultiLabelGCN on GB300 — fp16 m16n8k16 fused layers (2 CTAs/SM).
// Per CTA: M = 66 rows (2 graphs), N = 256, K in 8 chunks of 32 (2 k16 steps).
//   input triple-buffered cp.async; agg (BN+ReLU+stencil) computes float2,
//   packs fp16x2 A-fragments directly in mma register layout (LDS.128 read);
//   B fragments LDG.64 from packed fp16 weights (L2-resident).
// fp16 has the same 10-bit mantissa as tf32 -> same rel_err, half the instrs.
// ---------------------------------------------------------------------------

#define NUM_JOINTS 33
#define BATCH      4096
#define NN_ROWS    (BATCH * NUM_JOINTS)   // 135168
#define HDIM       256
#define NN_INV     (1.0f / 135168.0f)

#define NTILES (NN_ROWS / 66)       // 2048 CTAs
#define TROWS  66                   // 2 graphs
#define MPAD   80                   // 5 x m16

// smem layout (bytes)
#define OFF_IN     0                        // float [3][66][36]   28512
#define INBUF      9504
#define OFF_A2     28512                    // u32 [2][1280]       10240
#define OFF_SCALE  38752                    // float [256]          1024
#define OFF_SHIFT  39776                    // float [256]          1024
#define OFF_STAT   40800                    // float [512]          2048
#define OFF_NW     42848                    // float [103] + pad     512
#define SMEM_BYTES 43360

__constant__ int ADJ_OFF[34] = {
    0,3,6,9,12,15,18,21,23,25,27,29,33,37,40,43,48,53,56,59,62,65,
    67,69,73,77,80,83,87,91,94,97,100,103};
__constant__ int ADJ_NB[103] = {
    1,4,0,  0,2,1,  1,3,2,  2,7,3,  0,5,4,  4,6,5,  5,8,6,  3,7,  6,8,
    10,9,  9,10,  12,13,23,11,  11,14,24,12,  11,15,13,  12,16,14,
    13,17,19,21,15,  14,18,20,22,16,  15,19,17,  16,20,18,  15,17,19,
    16,18,20,  15,21,  16,22,  11,24,25,23,  12,23,26,24,  23,27,25,
    24,28,26,  25,29,31,27,  26,30,32,28,  27,31,29,  28,32,30,
    29,27,31,  30,28,32};
__constant__ float DEGF[33] = {
    3,3,3,3,3,3,3,2,2,2,2,4,4,3,3,5,5,3,3,3,3,2,2,4,4,3,3,4,4,3,3,3,3};

// scratch
__device__ float g_bufA[(size_t)NN_ROWS * HDIM];
__device__ float g_bufB[(size_t)NN_ROWS * HDIM];
__device__ float g_stats[3 * 512];
__device__ uint2 g_wpackH[4 * 8 * 32 * 2 * 32];  // [mat][chunk][ntile][s][lane]

// ---------------------------------------------------------------------------
__device__ __forceinline__ uint32_t pack_h2(float a, float b) {
    __half2 h = __float22half2_rn(make_float2(a, b));
    return *(uint32_t*)&h;
}
__device__ __forceinline__ void mma_f16(float* d, const uint32_t* a, const uint32_t* b) {
    asm volatile(
        "mma.sync.aligned.m16n8k16.row.col.f32.f16.f16.f32 "
        "{%0,%1,%2,%3}, {%4,%5,%6,%7}, {%8,%9}, {%0,%1,%2,%3};\n"
        : "+f"(d[0]), "+f"(d[1]), "+f"(d[2]), "+f"(d[3])
        : "r"(a[0]), "r"(a[1]), "r"(a[2]), "r"(a[3]), "r"(b[0]), "r"(b[1]));
}
__device__ __forceinline__ void cp16(void* dst, const void* src) {
    uint32_t d = (uint32_t)__cvta_generic_to_shared(dst);
    asm volatile("cp.async.cg.shared.global [%0], [%1], 16;\n" :: "r"(d), "l"(src));
}
#define CP_COMMIT() asm volatile("cp.async.commit_group;\n")
#define CP_WAIT1()  asm volatile("cp.async.wait_group 1;\n")

__device__ __forceinline__ float fixv(float f) {
    if (isnan(f)) return 0.0f;
    if (isinf(f)) return (f > 0.0f) ? FLT_MAX : -FLT_MAX;
    return f;
}

// ---------------------------------------------------------------------------
// pack weights -> fp16 B fragments: entry (m,c,ntile,s,lane):
//   n = ntile*8 + lane/4, t = lane%4, k0 = c*32 + s*16
//   v.x = {W[k0+2t][n], W[k0+2t+1][n]}   v.y = {W[k0+2t+8][n], W[k0+2t+9][n]}
// ---------------------------------------------------------------------------
__global__ void pack_w(const float* __restrict__ w0, const float* __restrict__ w1,
                       const float* __restrict__ w2, const float* __restrict__ wh)
{
    int idx = blockIdx.x * blockDim.x + threadIdx.x;   // 0..65535
    int lane  = idx & 31;
    int s     = (idx >> 5) & 1;
    int ntile = (idx >> 6) & 31;
    int c     = (idx >> 11) & 7;
    int m     = idx >> 14;
    const float* W = (m == 0) ? w0 : (m == 1) ? w1 : (m == 2) ? w2 : wh;
    int k0 = c * 32 + s * 16;
    int n  = ntile * 8 + (lane >> 2);
    int t  = lane & 3;
    uint2 v;
    v.x = pack_h2(W[(size_t)(k0 + 2*t)     * HDIM + n], W[(size_t)(k0 + 2*t + 1) * HDIM + n]);
    v.y = pack_h2(W[(size_t)(k0 + 2*t + 8) * HDIM + n], W[(size_t)(k0 + 2*t + 9) * HDIM + n]);
    g_wpackH[idx] = v;
}

__global__ void zero_stats_kernel(float* stats) {
    int i = blockIdx.x * blockDim.x + threadIdx.x;
    if (i < 3 * 512) stats[i] = 0.0f;
}

// ---------------------------------------------------------------------------
// fused layer. grid = NTILES (2048), block = 256, 2 CTAs/SM.
// ---------------------------------------------------------------------------
__global__ void __launch_bounds__(256, 2)
fused_layer(const float* __restrict__ in, int wsel, const float* __restrict__ bias,
            float* __restrict__ out, const float* __restrict__ stats_in,
            const float* __restrict__ gam, const float* __restrict__ bet,
            float* __restrict__ stats_out, int mode)
{
    extern __shared__ char smem[];
    float*    sIn   = (float*)(smem + OFF_IN);     // [3][66][36]
    uint32_t* sA2   = (uint32_t*)(smem + OFF_A2);  // [2][1280]
    float*    sScale= (float*)(smem + OFF_SCALE);
    float*    sShift= (float*)(smem + OFF_SHIFT);
    float*    sStat = (float*)(smem + OFF_STAT);
    float*    sNW   = (float*)(smem + OFF_NW);

    const int tid = threadIdx.x, lane = tid & 31, warp = tid >> 5;   // 8 warps
    const int p = blockIdx.x;
    const int rowBase = p * TROWS;
    const float* src = in + (size_t)rowBase * HDIM;
    const uint2* wbase = g_wpackH + (size_t)wsel * (8 * 32 * 2 * 32);

    // ---- init ----
    if (tid < NUM_JOINTS) {
        float dn = rsqrtf(DEGF[tid]);
        for (int e = ADJ_OFF[tid]; e < ADJ_OFF[tid + 1]; e++)
            sNW[e] = dn * rsqrtf(DEGF[ADJ_NB[e]]);
    }
    if (mode == 1) {
        float mu  = stats_in[tid] * NN_INV;
        float ex2 = stats_in[256 + tid] * NN_INV;
        float inv = rsqrtf(ex2 - mu * mu + 1e-5f);
        float sc  = inv * gam[tid];
        sScale[tid] = sc;
        sShift[tid] = bet[tid] - mu * sc;
    } else {
        sScale[tid] = 1.0f;
        sShift[tid] = 0.0f;
    }
    sStat[tid] = 0.0f;
    sStat[256 + tid] = 0.0f;
    // zero both A-fragment buffers (pad rows 66..79 stay zero forever)
    for (int i = tid; i < 2560; i += 256) sA2[i] = 0;

    // ---- prologue: stage in[0], in[1] ----
    for (int j = tid; j < TROWS * 8; j += 256) {
        int r = j >> 3, seg = j & 7;
        cp16((char*)sIn + r * 144 + seg * 16, src + (size_t)r * HDIM + seg * 4);
    }
    CP_COMMIT();
    for (int j = tid; j < TROWS * 8; j += 256) {
        int r = j >> 3, seg = j & 7;
        cp16((char*)sIn + INBUF + r * 144 + seg * 16,
             src + (size_t)r * HDIM + 32 + seg * 4);
    }
    CP_COMMIT();

    float acc[5][4][4];
    #pragma unroll
    for (int i = 0; i < 5; i++)
        #pragma unroll
        for (int nt = 0; nt < 4; nt++)
            #pragma unroll
            for (int j = 0; j < 4; j++) acc[i][nt][j] = 0.0f;

    const int pair = lane & 15;    // channel pair within chunk (chans 2p, 2p+1)
    const int half = lane >> 4;    // row offset selector

    for (int c = 0; c < 8; c++) {
        CP_WAIT1();
        __syncthreads();   // in[c] staged + visible; sA[c&1] free (MMA[c-2] done)

        // issue in[c+2]
        if (c + 2 < 8) {
            char* dI = (char*)sIn + ((c + 2) % 3) * INBUF;
            const float* sN = src + (c + 2) * 32;
            for (int j = tid; j < TROWS * 8; j += 256) {
                int r = j >> 3, seg = j & 7;
                cp16(dI + r * 144 + seg * 16, sN + (size_t)r * HDIM + seg * 4);
            }
        }
        CP_COMMIT();       // unconditional: uniform group accounting

        // ---- agg[c]: sIn[c%3] -> sA2[c&1] as fp16x2 mma fragments ----
        {
            const float* sInc = sIn + (c % 3) * (66 * 36);
            uint32_t* sAc = sA2 + (c & 1) * 1280;
            float2 scl2 = *(const float2*)&sScale[c * 32 + pair * 2];
            float2 shf2 = *(const float2*)&sShift[c * 32 + pair * 2];
            #pragma unroll
            for (int j = 0; j < 5; j++) {
                int r = warp + 16 * j + 8 * half;
                if (r < TROWS) {
                    int n  = (r >= NUM_JOINTS) ? r - NUM_JOINTS : r;
                    int lb = (r >= NUM_JOINTS) ? NUM_JOINTS : 0;
                    float ax = 0.0f, ay = 0.0f;
                    int e1 = ADJ_OFF[n + 1];
                    for (int e = ADJ_OFF[n]; e < e1; e++) {
                        float2 f = *(const float2*)&sInc[(lb + ADJ_NB[e]) * 36 + pair * 2];
                        float fx, fy;
                        if (mode == 0) {
                            fx = fixv(f.x); fy = fixv(f.y);
                        } else {
                            fx = fmaxf(fmaf(f.x, scl2.x, shf2.x), 0.0f);
                            fy = fmaxf(fmaf(f.y, scl2.y, shf2.y), 0.0f);
                        }
                        float w = sNW[e];
                        ax = fmaf(w, fx, ax);
                        ay = fmaf(w, fy, ay);
                    }
                    // fp16 range insurance
                    ax = fminf(fmaxf(ax, -60000.0f), 60000.0f);
                    ay = fminf(fmaxf(ay, -60000.0f), 60000.0f);
                    int tl   = r >> 4;
                    int s    = pair >> 3;
                    int lp   = (r & 7) * 4 + (pair & 3);
                    int comp = ((r >> 3) & 1) + (((pair >> 2) & 1) << 1);
                    sAc[((tl * 2 + s) * 32 + lp) * 4 + comp] = pack_h2(ax, ay);
                }
            }
        }
        __syncthreads();   // sA2[c&1] ready

        // ---- MMA[c]: A LDS.128 from smem, B LDG.64 from packed W (L2) ----
        {
            const uint32_t* sAc = sA2 + (c & 1) * 1280;
            #pragma unroll
            for (int s = 0; s < 2; s++) {
                uint2 bfr[4];
                #pragma unroll
                for (int nt = 0; nt < 4; nt++) {
                    int ntile = warp * 4 + nt;
                    bfr[nt] = __ldg(&wbase[((c * 32 + ntile) * 2 + s) * 32 + lane]);
                }
                #pragma unroll
                for (int tl = 0; tl < 5; tl++) {
                    uint4 av = *(const uint4*)&sAc[((tl * 2 + s) * 32 + lane) * 4];
                    const uint32_t* af = (const uint32_t*)&av;
                    #pragma unroll
                    for (int nt = 0; nt < 4; nt++)
                        mma_f16(acc[tl][nt], af, (const uint32_t*)&bfr[nt]);
                }
            }
        }
    }

    // ---- epilogue: bias, store, stats (warp covers cols warp*32..+31) ----
    float bval[8];
    #pragma unroll
    for (int nt = 0; nt < 4; nt++) {
        int col = warp * 32 + nt * 8 + 2 * (lane & 3);
        bval[nt * 2 + 0] = bias[col];
        bval[nt * 2 + 1] = bias[col + 1];
    }
    float cs1[8], cs2[8];
    #pragma unroll
    for (int j = 0; j < 8; j++) { cs1[j] = 0.0f; cs2[j] = 0.0f; }

    #pragma unroll
    for (int i = 0; i < 5; i++) {
        int rb = i * 16 + (lane >> 2);
        #pragma unroll
        for (int nt = 0; nt < 4; nt++) {
            int col = warp * 32 + nt * 8 + 2 * (lane & 3);
            if (rb < TROWS) {
                float z0 = acc[i][nt][0] + bval[nt * 2 + 0];
                float z1 = acc[i][nt][1] + bval[nt * 2 + 1];
                *(float2*)(out + (size_t)(rowBase + rb) * HDIM + col) = make_float2(z0, z1);
                cs1[nt * 2 + 0] += z0; cs2[nt * 2 + 0] = fmaf(z0, z0, cs2[nt * 2 + 0]);
                cs1[nt * 2 + 1] += z1; cs2[nt * 2 + 1] = fmaf(z1, z1, cs2[nt * 2 + 1]);
            }
            int r2 = rb + 8;
            if (r2 < TROWS) {
                float z2 = acc[i][nt][2] + bval[nt * 2 + 0];
                float z3 = acc[i][nt][3] + bval[nt * 2 + 1];
                *(float2*)(out + (size_t)(rowBase + r2) * HDIM + col) = make_float2(z2, z3);
                cs1[nt * 2 + 0] += z2; cs2[nt * 2 + 0] = fmaf(z2, z2, cs2[nt * 2 + 0]);
                cs1[nt * 2 + 1] += z3; cs2[nt * 2 + 1] = fmaf(z3, z3, cs2[nt * 2 + 1]);
            }
        }
    }

    if (stats_out != nullptr) {
        #pragma unroll
        for (int j = 0; j < 8; j++) {
            int cl = warp * 32 + (j >> 1) * 8 + 2 * (lane & 3) + (j & 1);
            atomicAdd(&sStat[cl], cs1[j]);
            atomicAdd(&sStat[256 + cl], cs2[j]);
        }
        __syncthreads();
        atomicAdd(&stats_out[tid], sStat[tid]);
        atomicAdd(&stats_out[256 + tid], sStat[256 + tid]);
    }
}

// ---------------------------------------------------------------------------
__global__ void __launch_bounds__(256)
pool_kernel(const float* __restrict__ h, const float* __restrict__ wc,
            const float* __restrict__ bc, float* __restrict__ out)
{
    const int g = blockIdx.x;
    const int tid = threadIdx.x;
    const int lane = tid & 31, warp = tid >> 5;
    const size_t base = (size_t)g * NUM_JOINTS * HDIM;

    float s = 0.0f;
    #pragma unroll
    for (int n = 0; n < NUM_JOINTS; n++) s += h[base + n * HDIM + tid];
    s *= (1.0f / 33.0f);

    float4 wv = *(const float4*)(wc + tid * 4);
    float p0 = s * wv.x, p1 = s * wv.y, p2 = s * wv.z, p3 = s * wv.w;
    #pragma unroll
    for (int off = 16; off > 0; off >>= 1) {
        p0 += __shfl_down_sync(0xFFFFFFFF, p0, off);
        p1 += __shfl_down_sync(0xFFFFFFFF, p1, off);
        p2 += __shfl_down_sync(0xFFFFFFFF, p2, off);
        p3 += __shfl_down_sync(0xFFFFFFFF, p3, off);
    }
    __shared__ float4 part[8];
    if (lane == 0) part[warp] = make_float4(p0, p1, p2, p3);
    __syncthreads();
    if (tid == 0) {
        float4 o = make_float4(bc[0], bc[1], bc[2], bc[3]);
        #pragma unroll
        for (int w = 0; w < 8; w++) {
            o.x += part[w].x; o.y += part[w].y; o.z += part[w].z; o.w += part[w].w;
        }
        *(float4*)(out + g * 4) = o;
    }
}

// ---------------------------------------------------------------------------
extern "C" void kernel_launch(void* const* d_in, const int* in_sizes, int n_in,
                              void* d_out, int out_size)
{
    const float* x   = (const float*)d_in[0];
    const float* w0  = (const float*)d_in[1];
    const float* b0  = (const float*)d_in[2];
    const float* g0  = (const float*)d_in[3];
    const float* be0 = (const float*)d_in[4];
    const float* w1  = (const float*)d_in[5];
    const float* b1  = (const float*)d_in[6];
    const float* g1  = (const float*)d_in[7];
    const float* be1 = (const float*)d_in[8];
    const float* w2  = (const float*)d_in[9];
    const float* b2  = (const float*)d_in[10];
    const float* g2  = (const float*)d_in[11];
    const float* be2 = (const float*)d_in[12];
    const float* wh  = (const float*)d_in[13];
    const float* bh  = (const float*)d_in[14];
    const float* wc  = (const float*)d_in[15];
    const float* bc  = (const float*)d_in[16];

    float *bufA, *bufB, *stats;
    cudaGetSymbolAddress((void**)&bufA, g_bufA);
    cudaGetSymbolAddress((void**)&bufB, g_bufB);
    cudaGetSymbolAddress((void**)&stats, g_stats);

    cudaFuncSetAttribute(fused_layer, cudaFuncAttributeMaxDynamicSharedMemorySize,
                         SMEM_BYTES);

    pack_w<<<256, 256>>>(w0, w1, w2, wh);
    zero_stats_kernel<<<6, 256>>>(stats);

    fused_layer<<<NTILES, 256, SMEM_BYTES>>>(x,    0, b0, bufB, nullptr, nullptr, nullptr, stats, 0);
    fused_layer<<<NTILES, 256, SMEM_BYTES>>>(bufB, 1, b1, bufA, stats,        g0, be0, stats + 512, 1);
    fused_layer<<<NTILES, 256, SMEM_BYTES>>>(bufA, 2, b2, bufB, stats + 512,  g1, be1, stats + 1024, 1);
    fused_layer<<<NTILES, 256, SMEM_BYTES>>>(bufB, 3, bh, bufA, stats + 1024, g2, be2, nullptr, 1);
    pool_kernel<<<BATCH, 256>>>(bufA, wc, bc, (float*)d_out);
}

// round 11
// speedup vs baseline: 1.7002x; 1.0735x over previous
#include <cuda_runtime.h>
#include <cuda_bf16.h>
#include <cuda_fp16.h>
#include <math.h>
#include <float.h>
#include <stdint.h>

// ---------------------------------------------------------------------------
// MultiLabelGCN on GB300 — fp16 m16n8k16 fused layers (2 CTAs/SM).
// R11: BN+ReLU applied ONCE per staged element (in-place transform phase),
//      agg inner loop = pure LDS+FMA; B fragments prefetched into registers
//      at chunk start so L2 latency hides under transform+agg.
// ---------------------------------------------------------------------------

#define NUM_JOINTS 33
#define BATCH      4096
#define NN_ROWS    (BATCH * NUM_JOINTS)   // 135168
#define HDIM       256
#define NN_INV     (1.0f / 135168.0f)

#define NTILES (NN_ROWS / 66)       // 2048 CTAs
#define TROWS  66                   // 2 graphs
#define MPAD   80                   // 5 x m16

// smem layout (bytes)
#define OFF_IN     0                        // float [3][66][36]   28512
#define INBUF      9504
#define OFF_A2     28512                    // u32 [2][1280]       10240
#define OFF_SCALE  38752                    // float [256]          1024
#define OFF_SHIFT  39776                    // float [256]          1024
#define OFF_STAT   40800                    // float [512]          2048
#define OFF_NW     42848                    // float [103] + pad     512
#define SMEM_BYTES 43360

__constant__ int ADJ_OFF[34] = {
    0,3,6,9,12,15,18,21,23,25,27,29,33,37,40,43,48,53,56,59,62,65,
    67,69,73,77,80,83,87,91,94,97,100,103};
__constant__ int ADJ_NB[103] = {
    1,4,0,  0,2,1,  1,3,2,  2,7,3,  0,5,4,  4,6,5,  5,8,6,  3,7,  6,8,
    10,9,  9,10,  12,13,23,11,  11,14,24,12,  11,15,13,  12,16,14,
    13,17,19,21,15,  14,18,20,22,16,  15,19,17,  16,20,18,  15,17,19,
    16,18,20,  15,21,  16,22,  11,24,25,23,  12,23,26,24,  23,27,25,
    24,28,26,  25,29,31,27,  26,30,32,28,  27,31,29,  28,32,30,
    29,27,31,  30,28,32};
__constant__ float DEGF[33] = {
    3,3,3,3,3,3,3,2,2,2,2,4,4,3,3,5,5,3,3,3,3,2,2,4,4,3,3,4,4,3,3,3,3};

// scratch
__device__ float g_bufA[(size_t)NN_ROWS * HDIM];
__device__ float g_bufB[(size_t)NN_ROWS * HDIM];
__device__ float g_stats[3 * 512];
__device__ uint2 g_wpackH[4 * 8 * 32 * 2 * 32];  // [mat][chunk][ntile][s][lane]

// ---------------------------------------------------------------------------
__device__ __forceinline__ uint32_t pack_h2(float a, float b) {
    __half2 h = __float22half2_rn(make_float2(a, b));
    return *(uint32_t*)&h;
}
__device__ __forceinline__ void mma_f16(float* d, const uint32_t* a, const uint32_t* b) {
    asm volatile(
        "mma.sync.aligned.m16n8k16.row.col.f32.f16.f16.f32 "
        "{%0,%1,%2,%3}, {%4,%5,%6,%7}, {%8,%9}, {%0,%1,%2,%3};\n"
        : "+f"(d[0]), "+f"(d[1]), "+f"(d[2]), "+f"(d[3])
        : "r"(a[0]), "r"(a[1]), "r"(a[2]), "r"(a[3]), "r"(b[0]), "r"(b[1]));
}
__device__ __forceinline__ void cp16(void* dst, const void* src) {
    uint32_t d = (uint32_t)__cvta_generic_to_shared(dst);
    asm volatile("cp.async.cg.shared.global [%0], [%1], 16;\n" :: "r"(d), "l"(src));
}
#define CP_COMMIT() asm volatile("cp.async.commit_group;\n")
#define CP_WAIT1()  asm volatile("cp.async.wait_group 1;\n")

__device__ __forceinline__ float fixv(float f) {
    if (isnan(f)) return 0.0f;
    if (isinf(f)) return (f > 0.0f) ? FLT_MAX : -FLT_MAX;
    return f;
}

// ---------------------------------------------------------------------------
// pack weights -> fp16 B fragments (layout unchanged from R10, verified)
// ---------------------------------------------------------------------------
__global__ void pack_w(const float* __restrict__ w0, const float* __restrict__ w1,
                       const float* __restrict__ w2, const float* __restrict__ wh)
{
    int idx = blockIdx.x * blockDim.x + threadIdx.x;   // 0..65535
    int lane  = idx & 31;
    int s     = (idx >> 5) & 1;
    int ntile = (idx >> 6) & 31;
    int c     = (idx >> 11) & 7;
    int m     = idx >> 14;
    const float* W = (m == 0) ? w0 : (m == 1) ? w1 : (m == 2) ? w2 : wh;
    int k0 = c * 32 + s * 16;
    int n  = ntile * 8 + (lane >> 2);
    int t  = lane & 3;
    uint2 v;
    v.x = pack_h2(W[(size_t)(k0 + 2*t)     * HDIM + n], W[(size_t)(k0 + 2*t + 1) * HDIM + n]);
    v.y = pack_h2(W[(size_t)(k0 + 2*t + 8) * HDIM + n], W[(size_t)(k0 + 2*t + 9) * HDIM + n]);
    g_wpackH[idx] = v;
}

__global__ void zero_stats_kernel(float* stats) {
    int i = blockIdx.x * blockDim.x + threadIdx.x;
    if (i < 3 * 512) stats[i] = 0.0f;
}

// ---------------------------------------------------------------------------
// fused layer. grid = NTILES (2048), block = 256, 2 CTAs/SM.
// ---------------------------------------------------------------------------
__global__ void __launch_bounds__(256, 2)
fused_layer(const float* __restrict__ in, int wsel, const float* __restrict__ bias,
            float* __restrict__ out, const float* __restrict__ stats_in,
            const float* __restrict__ gam, const float* __restrict__ bet,
            float* __restrict__ stats_out, int mode)
{
    extern __shared__ char smem[];
    float*    sIn   = (float*)(smem + OFF_IN);     // [3][66][36]
    uint32_t* sA2   = (uint32_t*)(smem + OFF_A2);  // [2][1280]
    float*    sScale= (float*)(smem + OFF_SCALE);
    float*    sShift= (float*)(smem + OFF_SHIFT);
    float*    sStat = (float*)(smem + OFF_STAT);
    float*    sNW   = (float*)(smem + OFF_NW);

    const int tid = threadIdx.x, lane = tid & 31, warp = tid >> 5;   // 8 warps
    const int p = blockIdx.x;
    const int rowBase = p * TROWS;
    const float* src = in + (size_t)rowBase * HDIM;
    const uint2* wbase = g_wpackH + (size_t)wsel * (8 * 32 * 2 * 32);

    // ---- init ----
    if (tid < NUM_JOINTS) {
        float dn = rsqrtf(DEGF[tid]);
        for (int e = ADJ_OFF[tid]; e < ADJ_OFF[tid + 1]; e++)
            sNW[e] = dn * rsqrtf(DEGF[ADJ_NB[e]]);
    }
    if (mode == 1) {
        float mu  = stats_in[tid] * NN_INV;
        float ex2 = stats_in[256 + tid] * NN_INV;
        float inv = rsqrtf(ex2 - mu * mu + 1e-5f);
        float sc  = inv * gam[tid];
        sScale[tid] = sc;
        sShift[tid] = bet[tid] - mu * sc;
    } else {
        sScale[tid] = 1.0f;
        sShift[tid] = 0.0f;
    }
    sStat[tid] = 0.0f;
    sStat[256 + tid] = 0.0f;
    // zero both A-fragment buffers (pad rows stay zero forever)
    for (int i = tid; i < 2560; i += 256) sA2[i] = 0;

    // ---- prologue: stage in[0], in[1] ----
    for (int j = tid; j < TROWS * 8; j += 256) {
        int r = j >> 3, seg = j & 7;
        cp16((char*)sIn + r * 144 + seg * 16, src + (size_t)r * HDIM + seg * 4);
    }
    CP_COMMIT();
    for (int j = tid; j < TROWS * 8; j += 256) {
        int r = j >> 3, seg = j & 7;
        cp16((char*)sIn + INBUF + r * 144 + seg * 16,
             src + (size_t)r * HDIM + 32 + seg * 4);
    }
    CP_COMMIT();

    float acc[5][4][4];
    #pragma unroll
    for (int i = 0; i < 5; i++)
        #pragma unroll
        for (int nt = 0; nt < 4; nt++)
            #pragma unroll
            for (int j = 0; j < 4; j++) acc[i][nt][j] = 0.0f;

    const int pair = lane & 15;    // channel pair within chunk (chans 2p, 2p+1)
    const int half = lane >> 4;    // row offset selector

    for (int c = 0; c < 8; c++) {
        CP_WAIT1();
        __syncthreads();   // bar1: in[c] staged+visible; MMA[c-1] retired

        // ---- B[c] prefetch: L2 latency hides under transform + agg ----
        uint2 bfr[2][4];
        #pragma unroll
        for (int s = 0; s < 2; s++)
            #pragma unroll
            for (int nt = 0; nt < 4; nt++)
                bfr[s][nt] = __ldg(&wbase[((c * 32 + warp * 4 + nt) * 2 + s) * 32 + lane]);

        // ---- transform in[c] IN PLACE: BN+ReLU (or nan_to_num), once/elem ----
        {
            float* sInc = sIn + (c % 3) * (66 * 36);
            for (int j = tid; j < 1056; j += 256) {      // 66 rows x 16 pairs
                int r = j >> 4, pr = j & 15;
                float2* a = (float2*)&sInc[r * 36 + pr * 2];
                float2 f = *a;
                if (mode == 0) {
                    f.x = fixv(f.x); f.y = fixv(f.y);
                } else {
                    float2 sc = *(const float2*)&sScale[c * 32 + pr * 2];
                    float2 sh = *(const float2*)&sShift[c * 32 + pr * 2];
                    f.x = fmaxf(fmaf(f.x, sc.x, sh.x), 0.0f);
                    f.y = fmaxf(fmaf(f.y, sc.y, sh.y), 0.0f);
                }
                *a = f;
            }
        }

        // issue in[c+2] (victim buffer (c-1)%3, retired before bar1)
        if (c + 2 < 8) {
            char* dI = (char*)sIn + ((c + 2) % 3) * INBUF;
            const float* sN = src + (c + 2) * 32;
            for (int j = tid; j < TROWS * 8; j += 256) {
                int r = j >> 3, seg = j & 7;
                cp16(dI + r * 144 + seg * 16, sN + (size_t)r * HDIM + seg * 4);
            }
        }
        CP_COMMIT();       // unconditional: uniform group accounting

        __syncthreads();   // bar2: transformed in[c] visible

        // ---- agg[c]: pure stencil (LDS.64 + 2 FMA per edge) -> fragments ----
        {
            const float* sInc = sIn + (c % 3) * (66 * 36);
            uint32_t* sAc = sA2 + (c & 1) * 1280;
            #pragma unroll
            for (int j = 0; j < 5; j++) {
                int r = warp + 16 * j + 8 * half;
                if (r < TROWS) {
                    int n  = (r >= NUM_JOINTS) ? r - NUM_JOINTS : r;
                    int lb = (r >= NUM_JOINTS) ? NUM_JOINTS : 0;
                    float ax = 0.0f, ay = 0.0f;
                    int e1 = ADJ_OFF[n + 1];
                    for (int e = ADJ_OFF[n]; e < e1; e++) {
                        float2 f = *(const float2*)&sInc[(lb + ADJ_NB[e]) * 36 + pair * 2];
                        float w = sNW[e];
                        ax = fmaf(w, f.x, ax);
                        ay = fmaf(w, f.y, ay);
                    }
                    int tl   = r >> 4;
                    int s    = pair >> 3;
                    int lp   = (r & 7) * 4 + (pair & 3);
                    int comp = ((r >> 3) & 1) + (((pair >> 2) & 1) << 1);
                    sAc[((tl * 2 + s) * 32 + lp) * 4 + comp] = pack_h2(ax, ay);
                }
            }
        }
        __syncthreads();   // bar3: sA2[c&1] ready

        // ---- MMA[c]: A LDS.128 from smem, B from prefetched registers ----
        {
            const uint32_t* sAc = sA2 + (c & 1) * 1280;
            #pragma unroll
            for (int s = 0; s < 2; s++) {
                #pragma unroll
                for (int tl = 0; tl < 5; tl++) {
                    uint4 av = *(const uint4*)&sAc[((tl * 2 + s) * 32 + lane) * 4];
                    const uint32_t* af = (const uint32_t*)&av;
                    #pragma unroll
                    for (int nt = 0; nt < 4; nt++)
                        mma_f16(acc[tl][nt], af, (const uint32_t*)&bfr[s][nt]);
                }
            }
        }
    }

    // ---- epilogue: bias, store, stats (warp covers cols warp*32..+31) ----
    float bval[8];
    #pragma unroll
    for (int nt = 0; nt < 4; nt++) {
        int col = warp * 32 + nt * 8 + 2 * (lane & 3);
        bval[nt * 2 + 0] = bias[col];
        bval[nt * 2 + 1] = bias[col + 1];
    }
    float cs1[8], cs2[8];
    #pragma unroll
    for (int j = 0; j < 8; j++) { cs1[j] = 0.0f; cs2[j] = 0.0f; }

    #pragma unroll
    for (int i = 0; i < 5; i++) {
        int rb = i * 16 + (lane >> 2);
        #pragma unroll
        for (int nt = 0; nt < 4; nt++) {
            int col = warp * 32 + nt * 8 + 2 * (lane & 3);
            if (rb < TROWS) {
                float z0 = acc[i][nt][0] + bval[nt * 2 + 0];
                float z1 = acc[i][nt][1] + bval[nt * 2 + 1];
                *(float2*)(out + (size_t)(rowBase + rb) * HDIM + col) = make_float2(z0, z1);
                cs1[nt * 2 + 0] += z0; cs2[nt * 2 + 0] = fmaf(z0, z0, cs2[nt * 2 + 0]);
                cs1[nt * 2 + 1] += z1; cs2[nt * 2 + 1] = fmaf(z1, z1, cs2[nt * 2 + 1]);
            }
            int r2 = rb + 8;
            if (r2 < TROWS) {
                float z2 = acc[i][nt][2] + bval[nt * 2 + 0];
                float z3 = acc[i][nt][3] + bval[nt * 2 + 1];
                *(float2*)(out + (size_t)(rowBase + r2) * HDIM + col) = make_float2(z2, z3);
                cs1[nt * 2 + 0] += z2; cs2[nt * 2 + 0] = fmaf(z2, z2, cs2[nt * 2 + 0]);
                cs1[nt * 2 + 1] += z3; cs2[nt * 2 + 1] = fmaf(z3, z3, cs2[nt * 2 + 1]);
            }
        }
    }

    if (stats_out != nullptr) {
        #pragma unroll
        for (int j = 0; j < 8; j++) {
            int cl = warp * 32 + (j >> 1) * 8 + 2 * (lane & 3) + (j & 1);
            atomicAdd(&sStat[cl], cs1[j]);
            atomicAdd(&sStat[256 + cl], cs2[j]);
        }
        __syncthreads();
        atomicAdd(&stats_out[tid], sStat[tid]);
        atomicAdd(&stats_out[256 + tid], sStat[256 + tid]);
    }
}

// ---------------------------------------------------------------------------
__global__ void __launch_bounds__(256)
pool_kernel(const float* __restrict__ h, const float* __restrict__ wc,
            const float* __restrict__ bc, float* __restrict__ out)
{
    const int g = blockIdx.x;
    const int tid = threadIdx.x;
    const int lane = tid & 31, warp = tid >> 5;
    const size_t base = (size_t)g * NUM_JOINTS * HDIM;

    float s = 0.0f;
    #pragma unroll
    for (int n = 0; n < NUM_JOINTS; n++) s += h[base + n * HDIM + tid];
    s *= (1.0f / 33.0f);

    float4 wv = *(const float4*)(wc + tid * 4);
    float p0 = s * wv.x, p1 = s * wv.y, p2 = s * wv.z, p3 = s * wv.w;
    #pragma unroll
    for (int off = 16; off > 0; off >>= 1) {
        p0 += __shfl_down_sync(0xFFFFFFFF, p0, off);
        p1 += __shfl_down_sync(0xFFFFFFFF, p1, off);
        p2 += __shfl_down_sync(0xFFFFFFFF, p2, off);
        p3 += __shfl_down_sync(0xFFFFFFFF, p3, off);
    }
    __shared__ float4 part[8];
    if (lane == 0) part[warp] = make_float4(p0, p1, p2, p3);
    __syncthreads();
    if (tid == 0) {
        float4 o = make_float4(bc[0], bc[1], bc[2], bc[3]);
        #pragma unroll
        for (int w = 0; w < 8; w++) {
            o.x += part[w].x; o.y += part[w].y; o.z += part[w].z; o.w += part[w].w;
        }
        *(float4*)(out + g * 4) = o;
    }
}

// ---------------------------------------------------------------------------
extern "C" void kernel_launch(void* const* d_in, const int* in_sizes, int n_in,
                              void* d_out, int out_size)
{
    const float* x   = (const float*)d_in[0];
    const float* w0  = (const float*)d_in[1];
    const float* b0  = (const float*)d_in[2];
    const float* g0  = (const float*)d_in[3];
    const float* be0 = (const float*)d_in[4];
    const float* w1  = (const float*)d_in[5];
    const float* b1  = (const float*)d_in[6];
    const float* g1  = (const float*)d_in[7];
    const float* be1 = (const float*)d_in[8];
    const float* w2  = (const float*)d_in[9];
    const float* b2  = (const float*)d_in[10];
    const float* g2  = (const float*)d_in[11];
    const float* be2 = (const float*)d_in[12];
    const float* wh  = (const float*)d_in[13];
    const float* bh  = (const float*)d_in[14];
    const float* wc  = (const float*)d_in[15];
    const float* bc  = (const float*)d_in[16];

    float *bufA, *bufB, *stats;
    cudaGetSymbolAddress((void**)&bufA, g_bufA);
    cudaGetSymbolAddress((void**)&bufB, g_bufB);
    cudaGetSymbolAddress((void**)&stats, g_stats);

    cudaFuncSetAttribute(fused_layer, cudaFuncAttributeMaxDynamicSharedMemorySize,
                         SMEM_BYTES);

    pack_w<<<256, 256>>>(w0, w1, w2, wh);
    zero_stats_kernel<<<6, 256>>>(stats);

    fused_layer<<<NTILES, 256, SMEM_BYTES>>>(x,    0, b0, bufB, nullptr, nullptr, nullptr, stats, 0);
    fused_layer<<<NTILES, 256, SMEM_BYTES>>>(bufB, 1, b1, bufA, stats,        g0, be0, stats + 512, 1);
    fused_layer<<<NTILES, 256, SMEM_BYTES>>>(bufA, 2, b2, bufB, stats + 512,  g1, be1, stats + 1024, 1);
    fused_layer<<<NTILES, 256, SMEM_BYTES>>>(bufB, 3, bh, bufA, stats + 1024, g2, be2, nullptr, 1);
    pool_kernel<<<BATCH, 256>>>(bufA, wc, bc, (float*)d_out);
}